// round 3
// baseline (speedup 1.0000x reference)
#include <cuda_runtime.h>
#include <math.h>

#define Vv      40
#define Ee      512
#define Hh      512
#define DKk     512
#define DVv     512
#define TENC    8192
#define MAXLEN  200
#define EOSI    38
#define SCALE   0.04419417382415922f   /* 1/sqrt(512) */

#define NB      128          /* 8192/128 = 64 keys, 512/128 = 4 h-rows per block */
#define TPB     1024
#define ROWS_PB 4
#define KEYS_PB 64

// -------- persistent device scratch --------
__device__ float    g_GIT[Vv*3*Hh];     // transposed: [best][1536]
__device__ float    g_WV[TENC*Vv];      // values @ w_out[:, :512]^T  [8192][40]
__device__ float    g_h[Hh];            // current hidden (single buffer, safe per flag protocol)
__device__ float    g_pU[Vv*NB];        // partials, layout [k][block]
__device__ float    g_pDen[NB];         // per-block denom partials
__device__ float    g_pOutH[Vv];        // w_out[:,512:] @ h
__device__ unsigned g_flags[NB*32];     // per-block epoch flag, 128B padded

// -------- release/acquire flag ops --------
__device__ __forceinline__ void relstore(unsigned* p, unsigned v) {
    asm volatile("st.release.gpu.u32 [%0], %1;" :: "l"(p), "r"(v) : "memory");
}
__device__ __forceinline__ unsigned acqload(unsigned* p) {
    unsigned v;
    asm volatile("ld.acquire.gpu.u32 %0, [%1];" : "=r"(v) : "l"(p) : "memory");
    return v;
}

// warp-0 poll: lane l watches flags l, l+32, l+64, l+96
__device__ __forceinline__ void waitflags(int lane, unsigned tgt)
{
    for (;;) {
        unsigned a = acqload(&g_flags[(lane      )*32]);
        unsigned b = acqload(&g_flags[(lane + 32 )*32]);
        unsigned c = acqload(&g_flags[(lane + 64 )*32]);
        unsigned d = acqload(&g_flags[(lane + 96 )*32]);
        unsigned m = min(min(a, b), min(c, d));
        if (__all_sync(0xffffffffu, m >= tgt)) break;
    }
}

__global__ void init_kernel()
{
    for (int i = threadIdx.x; i < NB*32; i += blockDim.x) g_flags[i] = 0u;
}

// -------- GIT[v][gid] = dot(w_ih[gid], embed[v]) + b_ih[gid] ----------------
__global__ void gi_kernel(const float* __restrict__ w_ih,
                          const float* __restrict__ b_ih,
                          const float* __restrict__ embed)
{
    extern __shared__ float sE[];              // embed [40][512] = 80 KB
    for (int i = threadIdx.x; i < Vv*Ee; i += blockDim.x) sE[i] = embed[i];
    __syncthreads();

    int lane = threadIdx.x & 31;
    int gid  = blockIdx.x * (blockDim.x >> 5) + (threadIdx.x >> 5);
    if (gid >= 3*Hh) return;

    float4 wreg[4];
    const float4* wr = (const float4*)(w_ih + (size_t)gid * Ee);
    #pragma unroll
    for (int j = 0; j < 4; ++j) wreg[j] = wr[lane + 32*j];
    float bb = b_ih[gid];

    for (int v = 0; v < Vv; ++v) {
        const float4* ev = (const float4*)(sE + v*Ee);
        float a = 0.f;
        #pragma unroll
        for (int j = 0; j < 4; ++j) {
            float4 e = ev[lane + 32*j];
            a = fmaf(wreg[j].x, e.x, a); a = fmaf(wreg[j].y, e.y, a);
            a = fmaf(wreg[j].z, e.z, a); a = fmaf(wreg[j].w, e.w, a);
        }
        #pragma unroll
        for (int o = 16; o > 0; o >>= 1) a += __shfl_down_sync(0xffffffffu, a, o);
        if (lane == 0) g_GIT[(size_t)v*(3*Hh) + gid] = a + bb;   // transposed
    }
}

// -------- WV[t][k] = dot(values[t], w_out[k][0:512]) ------------------------
__global__ void wv_kernel(const float* __restrict__ enc,
                          const float* __restrict__ w_out)
{
    extern __shared__ float sW[];              // w_out[:, :512] [40][512] = 80 KB
    for (int i = threadIdx.x; i < Vv*DVv; i += blockDim.x) {
        int k = i / DVv, j = i % DVv;
        sW[i] = w_out[(size_t)k*(DVv+Hh) + j];
    }
    __syncthreads();

    int lane  = threadIdx.x & 31;
    int gw    = blockIdx.x * (blockDim.x >> 5) + (threadIdx.x >> 5);
    int wspan = gridDim.x  * (blockDim.x >> 5);

    for (int t = gw; t < TENC; t += wspan) {
        float4 vreg[4];
        const float4* vr = (const float4*)(enc + (size_t)t*(DKk+DVv) + DKk);
        #pragma unroll
        for (int j = 0; j < 4; ++j) vreg[j] = vr[lane + 32*j];
        for (int k = 0; k < Vv; ++k) {
            const float4* wk = (const float4*)(sW + k*DVv);
            float a = 0.f;
            #pragma unroll
            for (int j = 0; j < 4; ++j) {
                float4 w = wk[lane + 32*j];
                a = fmaf(vreg[j].x, w.x, a); a = fmaf(vreg[j].y, w.y, a);
                a = fmaf(vreg[j].z, w.z, a); a = fmaf(vreg[j].w, w.w, a);
            }
            #pragma unroll
            for (int o = 16; o > 0; o >>= 1) a += __shfl_down_sync(0xffffffffu, a, o);
            if (lane == 0) g_WV[(size_t)t*Vv + k] = a;
        }
    }
}

// -------- persistent decoder ------------------------------------------------
__global__ void __launch_bounds__(TPB, 1)
dec_main(const float* __restrict__ enc,
         const float* __restrict__ hidden,
         const float* __restrict__ w_hh,
         const float* __restrict__ b_hh,
         const float* __restrict__ w_out,
         const float* __restrict__ b_out,
         float*       __restrict__ dout)
{
    __shared__ float h_sh[Hh];
    __shared__ float sGH[ROWS_PB][3];
    __shared__ float sU[32][41];
    __shared__ float sDen[32];
    __shared__ float sR[Vv][13];
    __shared__ float sOH[Vv];
    __shared__ float s_invden;
    __shared__ int   s_best;

    const int tid  = threadIdx.x;
    const int wid  = tid >> 5;
    const int lane = tid & 31;
    const int b    = blockIdx.x;

    float* attn = dout + (MAXLEN*Vv + 1);
    const int t0   = b * KEYS_PB;
    const int row0 = b * ROWS_PB;
    int  mylen = MAXLEN;
    int  best  = EOSI;

    // ---- preload h(-1) = hidden; compute gh = w_hh @ hidden ----
    if (tid < Hh/4) ((float4*)h_sh)[tid] = ((const float4*)hidden)[tid];
    __syncthreads();

    #define COMPUTE_GH()                                                          \
    do {                                                                           \
        if (wid < 12) {                                                            \
            int rl = wid / 3, gate = wid % 3;                                      \
            const float4* wr = (const float4*)(w_hh +                              \
                               (size_t)(gate*Hh + row0 + rl) * Hh);                \
            const float4* hv4 = (const float4*)h_sh;                               \
            float a = 0.f;                                                         \
            _Pragma("unroll")                                                      \
            for (int j = 0; j < 4; ++j) {                                          \
                float4 w = wr[lane + 32*j], h = hv4[lane + 32*j];                  \
                a = fmaf(w.x, h.x, a); a = fmaf(w.y, h.y, a);                      \
                a = fmaf(w.z, h.z, a); a = fmaf(w.w, h.w, a);                      \
            }                                                                      \
            _Pragma("unroll")                                                      \
            for (int o = 16; o > 0; o >>= 1) a += __shfl_xor_sync(0xffffffffu, a, o); \
            if (lane == 0) sGH[rl][gate] = a;                                      \
        }                                                                          \
    } while (0)

    COMPUTE_GH();
    __syncthreads();

    for (int s = 0; s < MAXLEN; ++s) {
        // ---------------- stage A: combine (thread 0 only) ----------------
        if (tid == 0) {
            const float* git = g_GIT + (size_t)best * (3*Hh);
            float4 hn;
            float* hp = &hn.x;
            #pragma unroll
            for (int i = 0; i < ROWS_PB; ++i) {
                int row = row0 + i;
                float ghr = sGH[i][0] + b_hh[row];
                float ghz = sGH[i][1] + b_hh[Hh + row];
                float ghn = sGH[i][2] + b_hh[2*Hh + row];
                float gir = git[row], giz = git[Hh + row], gin = git[2*Hh + row];
                float rr = 1.f/(1.f + __expf(-(gir + ghr)));
                float zz = 1.f/(1.f + __expf(-(giz + ghz)));
                float x  = gin + rr*ghn;
                float e2 = __expf(2.f*x);
                float nn = (e2 - 1.f)/(e2 + 1.f);
                hp[i] = (1.f - zz)*nn + zz*h_sh[row];
            }
            __stcg((float4*)&g_h[row0], hn);       // same thread then releases:
            relstore(&g_flags[b*32], 2u*(unsigned)s + 1u);
        }

        // ---------------- stage B: attention ----------------
        if (wid == 0) waitflags(lane, 2u*(unsigned)s + 1u);
        __syncthreads();
        if (tid < Hh/4) ((float4*)h_sh)[tid] = __ldcg(((const float4*)g_h) + tid);
        __syncthreads();

        // blocks 1..40: one row of w_out[:,512:] @ h  (warp 31, before its keys)
        if (b >= 1 && b <= Vv && wid == 31) {
            int k = b - 1;
            const float4* wr  = (const float4*)(w_out + (size_t)k*(DVv+Hh) + DVv);
            const float4* hv4 = (const float4*)h_sh;
            float acc = 0.f;
            #pragma unroll
            for (int j = 0; j < 4; ++j) {
                float4 w = wr[lane + 32*j], h = hv4[lane + 32*j];
                acc = fmaf(w.x, h.x, acc); acc = fmaf(w.y, h.y, acc);
                acc = fmaf(w.z, h.z, acc); acc = fmaf(w.w, h.w, acc);
            }
            #pragma unroll
            for (int o = 16; o > 0; o >>= 1) acc += __shfl_xor_sync(0xffffffffu, acc, o);
            if (lane == 0) __stcg(&g_pOutH[k], acc);
        }

        {
            const float4* hv4 = (const float4*)h_sh;
            float4 h0 = hv4[lane], h1 = hv4[lane+32], h2 = hv4[lane+64], h3 = hv4[lane+96];
            float acc0 = 0.f, acc1 = 0.f, den = 0.f;
            #pragma unroll
            for (int it = 0; it < 2; ++it) {
                int t = t0 + wid + it*32;
                const float4* kr = (const float4*)(enc + (size_t)t*(DKk+DVv));
                float4 k0 = kr[lane], k1 = kr[lane+32], k2 = kr[lane+64], k3 = kr[lane+96];
                float a = 0.f;
                a = fmaf(k0.x, h0.x, a); a = fmaf(k0.y, h0.y, a);
                a = fmaf(k0.z, h0.z, a); a = fmaf(k0.w, h0.w, a);
                a = fmaf(k1.x, h1.x, a); a = fmaf(k1.y, h1.y, a);
                a = fmaf(k1.z, h1.z, a); a = fmaf(k1.w, h1.w, a);
                a = fmaf(k2.x, h2.x, a); a = fmaf(k2.y, h2.y, a);
                a = fmaf(k2.z, h2.z, a); a = fmaf(k2.w, h2.w, a);
                a = fmaf(k3.x, h3.x, a); a = fmaf(k3.y, h3.y, a);
                a = fmaf(k3.z, h3.z, a); a = fmaf(k3.w, h3.w, a);
                #pragma unroll
                for (int o = 16; o > 0; o >>= 1) a += __shfl_xor_sync(0xffffffffu, a, o);
                float e = __expf(a * SCALE);
                if (lane == 0) attn[(size_t)s*TENC + t] = e;   // unnormalized
                den += e;
                acc0 = fmaf(e, g_WV[(size_t)t*Vv + lane], acc0);
                if (lane < Vv - 32)
                    acc1 = fmaf(e, g_WV[(size_t)t*Vv + 32 + lane], acc1);
            }
            sU[wid][lane] = acc0;
            if (lane < Vv - 32) sU[wid][32 + lane] = acc1;
            if (lane == 0) sDen[wid] = den;
        }
        __syncthreads();

        if (tid < Vv) {
            float a = 0.f;
            #pragma unroll
            for (int w = 0; w < 32; ++w) a += sU[w][tid];
            __stcg(&g_pU[tid*NB + b], a);
        } else if (tid == Vv) {
            float d = 0.f;
            #pragma unroll
            for (int w = 0; w < 32; ++w) d += sDen[w];
            __stcg(&g_pDen[b], d);
        }
        __syncthreads();
        if (tid == 0) relstore(&g_flags[b*32], 2u*(unsigned)s + 2u);

        // gh for next step (off the critical path: after the flag release)
        if (s < MAXLEN-1) COMPUTE_GH();

        // ---------------- stage C: reduce + argmax ----------------
        if (wid == 0) waitflags(lane, 2u*(unsigned)s + 2u);
        __syncthreads();

        if (tid < 480) {
            int k = tid / 12, j = tid % 12;
            float a = 0.f;
            for (int p = j; p < NB; p += 12) a += __ldcg(&g_pU[k*NB + p]);
            sR[k][j] = a;
        } else if (tid >= 480 && tid < 480 + Vv) {
            sOH[tid - 480] = __ldcg(&g_pOutH[tid - 480]);
        } else if (tid >= 992) {
            int j = tid - 992;
            float d = 0.f;
            #pragma unroll
            for (int p = 0; p < NB/32; ++p) d += __ldcg(&g_pDen[j + 32*p]);
            #pragma unroll
            for (int o = 16; o > 0; o >>= 1) d += __shfl_xor_sync(0xffffffffu, d, o);
            if (j == 0) s_invden = 1.0f / d;
        }
        __syncthreads();

        if (wid == 0) {
            float inv = s_invden;
            float v1, v2 = -3.4e38f;
            int   k1 = lane, k2 = lane + 32;
            {
                float a = 0.f;
                #pragma unroll
                for (int j = 0; j < 12; ++j) a += sR[k1][j];
                v1 = a*inv + sOH[k1] + b_out[k1];
                if (b == 0) dout[s*Vv + k1] = v1;
            }
            if (lane < Vv - 32) {
                float a = 0.f;
                #pragma unroll
                for (int j = 0; j < 12; ++j) a += sR[k2][j];
                v2 = a*inv + sOH[k2] + b_out[k2];
                if (b == 0) dout[s*Vv + k2] = v2;
            }
            float bv; int bi;
            if (v2 > v1) { bv = v2; bi = k2; } else { bv = v1; bi = k1; }
            #pragma unroll
            for (int o = 16; o > 0; o >>= 1) {
                float ov = __shfl_xor_sync(0xffffffffu, bv, o);
                int   oi = __shfl_xor_sync(0xffffffffu, bi, o);
                if (ov > bv || (ov == bv && oi < bi)) { bv = ov; bi = oi; }
            }
            if (lane == 0) s_best = bi;
        }
        // normalize this block's attention row (parallel with argmax warp)
        if (tid >= 128 && tid < 128 + KEYS_PB) {
            attn[(size_t)s*TENC + t0 + (tid - 128)] *= s_invden;
        }
        __syncthreads();
        best = s_best;
        if (b == 0 && tid == 0 && best == EOSI && mylen == MAXLEN) mylen = s;
    }

    if (b == 0 && tid == 0) dout[MAXLEN*Vv] = (float)mylen;   // lens
}

// ---------------------------------------------------------------------------
extern "C" void kernel_launch(void* const* d_in, const int* in_sizes, int n_in,
                              void* d_out, int out_size)
{
    const float* enc    = (const float*)d_in[0];
    const float* hidden = (const float*)d_in[1];
    const float* embed  = (const float*)d_in[2];
    const float* w_ih   = (const float*)d_in[3];
    const float* w_hh   = (const float*)d_in[4];
    const float* b_ih   = (const float*)d_in[5];
    const float* b_hh   = (const float*)d_in[6];
    const float* w_out  = (const float*)d_in[7];
    const float* b_out  = (const float*)d_in[8];
    float*       out    = (float*)d_out;

    cudaFuncSetAttribute(gi_kernel, cudaFuncAttributeMaxDynamicSharedMemorySize, 81920);
    cudaFuncSetAttribute(wv_kernel, cudaFuncAttributeMaxDynamicSharedMemorySize, 81920);

    init_kernel<<<1, 256>>>();
    gi_kernel<<<192, 256, 81920>>>(w_ih, b_ih, embed);
    wv_kernel<<<256, 256, 81920>>>(enc, w_out);
    dec_main<<<NB, TPB>>>(enc, hidden, w_hh, b_hh, w_out, b_out, out);
}

// round 4
// speedup vs baseline: 1.3692x; 1.3692x over previous
#include <cuda_runtime.h>
#include <math.h>

#define Vv      40
#define Ee      512
#define Hh      512
#define DKk     512
#define DVv     512
#define TENC    8192
#define MAXLEN  200
#define EOSI    38
#define SCALE   0.04419417382415922f   /* 1/sqrt(512) */

#define NB      128          /* 64 keys, 4 h-rows per block */
#define TPB     1024
#define ROWS_PB 4
#define KEYS_PB 64

// -------- persistent device scratch --------
__device__ float  g_GIT[Vv*3*Hh];       // [best][1536]
__device__ float  g_WV[TENC*Vv];        // values @ w_out[:, :512]^T
__device__ float4 g_hT4[Hh/2];          // {h2i, tag, h2i+1, tag}
__device__ float2 g_pUT[(Vv+1)*NB];     // rows 0..39: pU, row 40: denom; {val, tag}
__device__ float2 g_pOHT[Vv];           // {w_out[:,512:]@h row, tag}
__device__ float4 g_verdict;            // {best, invden, tag, 0}

// -------- weak L2-direct vector ops (volatile: no hoisting, no L1, no fences)
__device__ __forceinline__ float2 ldcg2(const float2* p) {
    float2 v;
    asm volatile("ld.global.cg.v2.f32 {%0,%1},[%2];"
                 : "=f"(v.x), "=f"(v.y) : "l"(p) : "memory");
    return v;
}
__device__ __forceinline__ float4 ldcg4(const float4* p) {
    float4 v;
    asm volatile("ld.global.cg.v4.f32 {%0,%1,%2,%3},[%4];"
                 : "=f"(v.x), "=f"(v.y), "=f"(v.z), "=f"(v.w) : "l"(p) : "memory");
    return v;
}
__device__ __forceinline__ void stcg2(float2* p, float2 v) {
    asm volatile("st.global.cg.v2.f32 [%0],{%1,%2};"
                 :: "l"(p), "f"(v.x), "f"(v.y) : "memory");
}
__device__ __forceinline__ void stcg4(float4* p, float4 v) {
    asm volatile("st.global.cg.v4.f32 [%0],{%1,%2,%3,%4};"
                 :: "l"(p), "f"(v.x), "f"(v.y), "f"(v.z), "f"(v.w) : "memory");
}

// -------- reset tags every launch (graph-replay safe) --------
__global__ void reset_kernel()
{
    int tid = threadIdx.x;
    for (int i = tid; i < (Vv+1)*NB; i += blockDim.x) g_pUT[i] = make_float2(0.f, 0.f);
    for (int i = tid; i < Hh/2;      i += blockDim.x) g_hT4[i] = make_float4(0.f,0.f,0.f,0.f);
    if (tid < Vv) g_pOHT[tid] = make_float2(0.f, 0.f);
    if (tid == 0) g_verdict = make_float4(0.f, 0.f, 0.f, 0.f);
}

// -------- GIT[v][gid] = dot(w_ih[gid], embed[v]) + b_ih[gid] ----------------
__global__ void gi_kernel(const float* __restrict__ w_ih,
                          const float* __restrict__ b_ih,
                          const float* __restrict__ embed)
{
    extern __shared__ float sE[];              // embed [40][512] = 80 KB
    for (int i = threadIdx.x; i < Vv*Ee; i += blockDim.x) sE[i] = embed[i];
    __syncthreads();

    int lane = threadIdx.x & 31;
    int gid  = blockIdx.x * (blockDim.x >> 5) + (threadIdx.x >> 5);
    if (gid >= 3*Hh) return;

    float4 wreg[4];
    const float4* wr = (const float4*)(w_ih + (size_t)gid * Ee);
    #pragma unroll
    for (int j = 0; j < 4; ++j) wreg[j] = wr[lane + 32*j];
    float bb = b_ih[gid];

    for (int v = 0; v < Vv; ++v) {
        const float4* ev = (const float4*)(sE + v*Ee);
        float a = 0.f;
        #pragma unroll
        for (int j = 0; j < 4; ++j) {
            float4 e = ev[lane + 32*j];
            a = fmaf(wreg[j].x, e.x, a); a = fmaf(wreg[j].y, e.y, a);
            a = fmaf(wreg[j].z, e.z, a); a = fmaf(wreg[j].w, e.w, a);
        }
        #pragma unroll
        for (int o = 16; o > 0; o >>= 1) a += __shfl_down_sync(0xffffffffu, a, o);
        if (lane == 0) g_GIT[(size_t)v*(3*Hh) + gid] = a + bb;
    }
}

// -------- WV[t][k] = dot(values[t], w_out[k][0:512]) ------------------------
__global__ void wv_kernel(const float* __restrict__ enc,
                          const float* __restrict__ w_out)
{
    extern __shared__ float sW[];              // w_out[:, :512] = 80 KB
    for (int i = threadIdx.x; i < Vv*DVv; i += blockDim.x) {
        int k = i / DVv, j = i % DVv;
        sW[i] = w_out[(size_t)k*(DVv+Hh) + j];
    }
    __syncthreads();

    int lane  = threadIdx.x & 31;
    int gw    = blockIdx.x * (blockDim.x >> 5) + (threadIdx.x >> 5);
    int wspan = gridDim.x  * (blockDim.x >> 5);

    for (int t = gw; t < TENC; t += wspan) {
        float4 vreg[4];
        const float4* vr = (const float4*)(enc + (size_t)t*(DKk+DVv) + DKk);
        #pragma unroll
        for (int j = 0; j < 4; ++j) vreg[j] = vr[lane + 32*j];
        for (int k = 0; k < Vv; ++k) {
            const float4* wk = (const float4*)(sW + k*DVv);
            float a = 0.f;
            #pragma unroll
            for (int j = 0; j < 4; ++j) {
                float4 w = wk[lane + 32*j];
                a = fmaf(vreg[j].x, w.x, a); a = fmaf(vreg[j].y, w.y, a);
                a = fmaf(vreg[j].z, w.z, a); a = fmaf(vreg[j].w, w.w, a);
            }
            #pragma unroll
            for (int o = 16; o > 0; o >>= 1) a += __shfl_down_sync(0xffffffffu, a, o);
            if (lane == 0) g_WV[(size_t)t*Vv + k] = a;
        }
    }
}

// -------- persistent decoder ------------------------------------------------
__global__ void __launch_bounds__(TPB, 1)
dec_main(const float* __restrict__ enc,
         const float* __restrict__ hidden,
         const float* __restrict__ w_hh,
         const float* __restrict__ b_hh,
         const float* __restrict__ w_out,
         const float* __restrict__ b_out,
         float*       __restrict__ dout)
{
    __shared__ float  h_sh[Hh];
    __shared__ float  sGH[ROWS_PB][3];
    __shared__ float  sU[32][41];
    __shared__ float  sDen[32];
    __shared__ float  sR[Vv+1][13];
    __shared__ float  sOH[Vv];
    __shared__ float4 s_vd;
    __shared__ float  s_invden;

    const int tid  = threadIdx.x;
    const int wid  = tid >> 5;
    const int lane = tid & 31;
    const int b    = blockIdx.x;

    float* attn = dout + (MAXLEN*Vv + 1);
    const int t0   = b * KEYS_PB;
    const int row0 = b * ROWS_PB;
    int  mylen = MAXLEN;                       // block0 tid0 only
    int  best  = EOSI;

    // ---- preload h(-1) = hidden; precompute gh = w_hh @ hidden ----
    if (tid < Hh/4) ((float4*)h_sh)[tid] = ((const float4*)hidden)[tid];
    __syncthreads();

    #define COMPUTE_GH()                                                          \
    do {                                                                           \
        if (wid < 12) {                                                            \
            int rl = wid / 3, gate = wid % 3;                                      \
            const float4* wr = (const float4*)(w_hh +                              \
                               (size_t)(gate*Hh + row0 + rl) * Hh);                \
            const float4* hv4g = (const float4*)h_sh;                              \
            float a = 0.f;                                                         \
            _Pragma("unroll")                                                      \
            for (int j = 0; j < 4; ++j) {                                          \
                float4 w = wr[lane + 32*j], h = hv4g[lane + 32*j];                 \
                a = fmaf(w.x, h.x, a); a = fmaf(w.y, h.y, a);                      \
                a = fmaf(w.z, h.z, a); a = fmaf(w.w, h.w, a);                      \
            }                                                                      \
            _Pragma("unroll")                                                      \
            for (int o = 16; o > 0; o >>= 1) a += __shfl_xor_sync(0xffffffffu, a, o); \
            if (lane == 0) sGH[rl][gate] = a;                                      \
        }                                                                          \
    } while (0)

    COMPUTE_GH();
    __syncthreads();

    for (int s = 0; s < MAXLEN; ++s) {
        const float tagf = (float)(s + 1);

        // ---- poll verdict(s-1): single hot 16B line ----
        if (s > 0) {
            const float ptag = (float)s;
            for (;;) {
                int ok = 1;
                if (tid == 0) { float4 v = ldcg4(&g_verdict); s_vd = v; ok = (v.z == ptag); }
                if (__syncthreads_and(ok)) break;
            }
            best = (int)s_vd.x;
            // normalize previous attn row (off combine path)
            if (tid >= 256 && tid < 256 + KEYS_PB) {
                float invp = s_vd.y;
                attn[(size_t)(s-1)*TENC + t0 + (tid - 256)] *= invp;
            }
        }

        // ---- combine: GRU gates for this block's 4 rows (tid 992) ----
        if (tid == 992) {
            const float* git = g_GIT + (size_t)best * (3*Hh);
            float hn[ROWS_PB];
            #pragma unroll
            for (int i = 0; i < ROWS_PB; ++i) {
                int row = row0 + i;
                float ghr = sGH[i][0] + b_hh[row];
                float ghz = sGH[i][1] + b_hh[Hh + row];
                float ghn = sGH[i][2] + b_hh[2*Hh + row];
                float gir = git[row], giz = git[Hh + row], gin = git[2*Hh + row];
                float rr = 1.f/(1.f + __expf(-(gir + ghr)));
                float zz = 1.f/(1.f + __expf(-(giz + ghz)));
                float x  = gin + rr*ghn;
                float e2 = __expf(2.f*x);
                float nn = (e2 - 1.f)/(e2 + 1.f);
                hn[i] = (1.f - zz)*nn + zz*h_sh[row];
            }
            stcg4(&g_hT4[2*b    ], make_float4(hn[0], tagf, hn[1], tagf));
            stcg4(&g_hT4[2*b + 1], make_float4(hn[2], tagf, hn[3], tagf));
        }

        // ---- poll all 128 blocks' tagged h chunks ----
        {
            float4 hv;
            for (;;) {
                int ok = 1;
                if (tid < Hh/2) {
                    hv = ldcg4(&g_hT4[tid]);
                    ok = (hv.y == tagf) && (hv.w == tagf);
                }
                if (__syncthreads_and(ok)) break;
            }
            if (tid < Hh/2) { h_sh[2*tid] = hv.x; h_sh[2*tid + 1] = hv.z; }
        }
        __syncthreads();

        // ---- attention over this block's 64 keys (L1-resident) ----
        if (b >= 1 && b <= Vv && wid == 31) {       // pOutH row b-1
            int k = b - 1;
            const float4* wr  = (const float4*)(w_out + (size_t)k*(DVv+Hh) + DVv);
            const float4* hv4 = (const float4*)h_sh;
            float acc = 0.f;
            #pragma unroll
            for (int j = 0; j < 4; ++j) {
                float4 w = wr[lane + 32*j], h = hv4[lane + 32*j];
                acc = fmaf(w.x, h.x, acc); acc = fmaf(w.y, h.y, acc);
                acc = fmaf(w.z, h.z, acc); acc = fmaf(w.w, h.w, acc);
            }
            #pragma unroll
            for (int o = 16; o > 0; o >>= 1) acc += __shfl_xor_sync(0xffffffffu, acc, o);
            if (lane == 0) stcg2(&g_pOHT[k], make_float2(acc, tagf));
        }
        {
            const float4* hv4 = (const float4*)h_sh;
            float4 h0 = hv4[lane], h1 = hv4[lane+32], h2 = hv4[lane+64], h3 = hv4[lane+96];
            float acc0 = 0.f, acc1 = 0.f, den = 0.f;
            #pragma unroll
            for (int it = 0; it < 2; ++it) {
                int t = t0 + wid + it*32;
                const float4* kr = (const float4*)(enc + (size_t)t*(DKk+DVv));
                float4 k0 = kr[lane], k1 = kr[lane+32], k2 = kr[lane+64], k3 = kr[lane+96];
                float a = 0.f;
                a = fmaf(k0.x, h0.x, a); a = fmaf(k0.y, h0.y, a);
                a = fmaf(k0.z, h0.z, a); a = fmaf(k0.w, h0.w, a);
                a = fmaf(k1.x, h1.x, a); a = fmaf(k1.y, h1.y, a);
                a = fmaf(k1.z, h1.z, a); a = fmaf(k1.w, h1.w, a);
                a = fmaf(k2.x, h2.x, a); a = fmaf(k2.y, h2.y, a);
                a = fmaf(k2.z, h2.z, a); a = fmaf(k2.w, h2.w, a);
                a = fmaf(k3.x, h3.x, a); a = fmaf(k3.y, h3.y, a);
                a = fmaf(k3.z, h3.z, a); a = fmaf(k3.w, h3.w, a);
                #pragma unroll
                for (int o = 16; o > 0; o >>= 1) a += __shfl_xor_sync(0xffffffffu, a, o);
                float e = __expf(a * SCALE);
                if (lane == 0) attn[(size_t)s*TENC + t] = e;   // unnormalized
                den += e;
                acc0 = fmaf(e, g_WV[(size_t)t*Vv + lane], acc0);
                if (lane < Vv - 32)
                    acc1 = fmaf(e, g_WV[(size_t)t*Vv + 32 + lane], acc1);
            }
            sU[wid][lane] = acc0;
            if (lane < Vv - 32) sU[wid][32 + lane] = acc1;
            if (lane == 0) sDen[wid] = den;
        }
        __syncthreads();

        if (tid < Vv) {
            float a = 0.f;
            #pragma unroll
            for (int w = 0; w < 32; ++w) a += sU[w][tid];
            stcg2(&g_pUT[tid*NB + b], make_float2(a, tagf));
        } else if (tid == Vv) {
            float d = 0.f;
            #pragma unroll
            for (int w = 0; w < 32; ++w) d += sDen[w];
            stcg2(&g_pUT[Vv*NB + b], make_float2(d, tagf));
        }

        // gh for next step — overlaps block 0's reduction
        if (s < MAXLEN-1) COMPUTE_GH();

        // ---- block 0: poll+accumulate partials, logits, argmax, publish ----
        if (b == 0) {
            float acc = 0.f;
            int k = 0, j = 0;
            if (tid < 492) { k = tid / 12; j = tid % 12; }
            for (;;) {
                int ok = 1;
                if (tid < 492) {
                    acc = 0.f; ok = 1;
                    for (int p = j; p < NB; p += 12) {
                        float2 e = ldcg2(&g_pUT[k*NB + p]);
                        ok &= (e.y == tagf);
                        acc += e.x;
                    }
                } else if (tid >= 512 && tid < 512 + Vv) {
                    float2 e = ldcg2(&g_pOHT[tid - 512]);
                    ok = (e.y == tagf);
                    sOH[tid - 512] = e.x;
                }
                if (__syncthreads_and(ok)) break;
            }
            if (tid < 492) sR[k][j] = acc;
            __syncthreads();
            if (tid == 0) {
                float d = 0.f;
                #pragma unroll
                for (int q = 0; q < 12; ++q) d += sR[Vv][q];
                s_invden = 1.0f / d;
            }
            __syncthreads();
            if (wid == 0) {
                float inv = s_invden;
                float v1, v2 = -3.4e38f;
                int   k1 = lane, k2 = lane + 32;
                {
                    float a = 0.f;
                    #pragma unroll
                    for (int q = 0; q < 12; ++q) a += sR[k1][q];
                    v1 = a*inv + sOH[k1] + b_out[k1];
                    dout[s*Vv + k1] = v1;
                }
                if (lane < Vv - 32) {
                    float a = 0.f;
                    #pragma unroll
                    for (int q = 0; q < 12; ++q) a += sR[k2][q];
                    v2 = a*inv + sOH[k2] + b_out[k2];
                    dout[s*Vv + k2] = v2;
                }
                float bv; int bi;
                if (v2 > v1) { bv = v2; bi = k2; } else { bv = v1; bi = k1; }
                #pragma unroll
                for (int o = 16; o > 0; o >>= 1) {
                    float ov = __shfl_xor_sync(0xffffffffu, bv, o);
                    int   oi = __shfl_xor_sync(0xffffffffu, bi, o);
                    if (ov > bv || (ov == bv && oi < bi)) { bv = ov; bi = oi; }
                }
                if (lane == 0) {
                    if (bi == EOSI && mylen == MAXLEN) mylen = s;
                    stcg4(&g_verdict, make_float4((float)bi, inv, tagf, 0.f));
                }
            }
        }
    }

    // ---- tail: poll final verdict, normalize last attn row, write lens ----
    {
        const float ptag = (float)MAXLEN;
        for (;;) {
            int ok = 1;
            if (tid == 0) { float4 v = ldcg4(&g_verdict); s_vd = v; ok = (v.z == ptag); }
            if (__syncthreads_and(ok)) break;
        }
        if (tid >= 256 && tid < 256 + KEYS_PB) {
            attn[(size_t)(MAXLEN-1)*TENC + t0 + (tid - 256)] *= s_vd.y;
        }
        if (b == 0 && tid == 0) dout[MAXLEN*Vv] = (float)mylen;
    }
}

// ---------------------------------------------------------------------------
extern "C" void kernel_launch(void* const* d_in, const int* in_sizes, int n_in,
                              void* d_out, int out_size)
{
    const float* enc    = (const float*)d_in[0];
    const float* hidden = (const float*)d_in[1];
    const float* embed  = (const float*)d_in[2];
    const float* w_ih   = (const float*)d_in[3];
    const float* w_hh   = (const float*)d_in[4];
    const float* b_ih   = (const float*)d_in[5];
    const float* b_hh   = (const float*)d_in[6];
    const float* w_out  = (const float*)d_in[7];
    const float* b_out  = (const float*)d_in[8];
    float*       out    = (float*)d_out;

    cudaFuncSetAttribute(gi_kernel, cudaFuncAttributeMaxDynamicSharedMemorySize, 81920);
    cudaFuncSetAttribute(wv_kernel, cudaFuncAttributeMaxDynamicSharedMemorySize, 81920);

    reset_kernel<<<1, 1024>>>();
    gi_kernel<<<192, 256, 81920>>>(w_ih, b_ih, embed);
    wv_kernel<<<256, 256, 81920>>>(enc, w_out);
    dec_main<<<NB, TPB>>>(enc, hidden, w_hh, b_hh, w_out, b_out, out);
}